// round 1
// baseline (speedup 1.0000x reference)
#include <cuda_runtime.h>
#include <cuda_bf16.h>

// TELIF: temporal-encoded LIF spiking neuron scan.
// tx: [T, B, N] float32, TE: [N, T] float32 -> out ty: [T, B, N] float32.
// Recurrence per (b, n):
//   th = th + v*TE[n,t] - (th - THRESHOLD)*BETA
//   v  = v*DECAY*(1-y) + tx[t,b,n]
//   y  = (v > th) ? 1 : 0
//
// Strategy: HBM-bound streaming. One thread per (b,n), sequential over t,
// loads front-batched (unroll 8) for MLP. TE transposed once to [T,N] so the
// per-step TE read is coalesced (native [N,T] layout would cost 32 L1tex
// wavefronts per warp-load and saturate L1tex).

#define T_STEPS 512
#define B_DIM   64
#define N_DIM   1024
#define BN      (B_DIM * N_DIM)

#define REST      0.0f
#define DECAY     0.2f
#define THRESHOLD 0.3f
#define BETA      0.02f

// Scratch for transposed TE (allocation-free rule: __device__ global).
__device__ float g_te_t[T_STEPS * N_DIM];  // [T][N]

// ---------------------------------------------------------------------------
// Transpose TE [N, T] -> g_te_t [T, N]. 32x32 tiles, padded smem.
// Grid: (N/32, T/32), Block: (32, 8).
// ---------------------------------------------------------------------------
__global__ void telif_transpose_te(const float* __restrict__ TE) {
    __shared__ float tile[32][33];
    int n0 = blockIdx.x * 32;
    int t0 = blockIdx.y * 32;
    int lx = threadIdx.x;
    int ly = threadIdx.y;

    // Read TE[n0+ly+i][t0+lx]  (coalesced along t)
#pragma unroll
    for (int i = 0; i < 32; i += 8) {
        tile[ly + i][lx] = TE[(size_t)(n0 + ly + i) * T_STEPS + (t0 + lx)];
    }
    __syncthreads();

    // Write g_te_t[t0+ly+i][n0+lx] (coalesced along n)
#pragma unroll
    for (int i = 0; i < 32; i += 8) {
        g_te_t[(size_t)(t0 + ly + i) * N_DIM + (n0 + lx)] = tile[lx][ly + i];
    }
}

// ---------------------------------------------------------------------------
// Main scan kernel. One thread per (b, n). 65536 threads total.
// ---------------------------------------------------------------------------
__global__ void __launch_bounds__(256, 8)
telif_scan(const float* __restrict__ tx, float* __restrict__ out) {
    const int idx = blockIdx.x * 256 + threadIdx.x;   // b*N + n
    const int n   = idx & (N_DIM - 1);

    const float* txp = tx + idx;
    float*       op  = out + idx;
    const float* tep = g_te_t + n;

    float v  = REST;
    float y  = 0.0f;
    float th = THRESHOLD;

#pragma unroll 1
    for (int t0 = 0; t0 < T_STEPS; t0 += 8) {
        float xs[8], te[8];
        // Front-batched independent loads: 16 outstanding LDGs -> MLP to hide
        // DRAM latency. tx loads are the streaming traffic; te loads hit L2.
#pragma unroll
        for (int u = 0; u < 8; u++) {
            xs[u] = txp[(size_t)(t0 + u) * BN];
            te[u] = tep[(size_t)(t0 + u) * N_DIM];
        }
#pragma unroll
        for (int u = 0; u < 8; u++) {
            th = th + v * te[u] - (th - THRESHOLD) * BETA;
            v  = v * DECAY * (1.0f - y) + xs[u];
            y  = (v > th) ? 1.0f : 0.0f;
            op[(size_t)(t0 + u) * BN] = y;
        }
    }
}

// ---------------------------------------------------------------------------
// Launch
// ---------------------------------------------------------------------------
extern "C" void kernel_launch(void* const* d_in, const int* in_sizes, int n_in,
                              void* d_out, int out_size) {
    const float* tx = (const float*)d_in[0];   // [T, B, N]
    const float* TE = (const float*)d_in[1];   // [N, T]
    float* out = (float*)d_out;                // [T, B, N]

    (void)in_sizes; (void)n_in; (void)out_size;

    dim3 tb(32, 8);
    dim3 tg(N_DIM / 32, T_STEPS / 32);
    telif_transpose_te<<<tg, tb>>>(TE);

    telif_scan<<<BN / 256, 256>>>(tx, out);
}